// round 9
// baseline (speedup 1.0000x reference)
#include <cuda_runtime.h>

// ---------------- problem constants ----------------
#define B_  16
#define A_  65536
#define G_  32
#define NBINS 4096
#define BIN_SCALE 819.2f            /* NBINS / 5.0 ; bce in [0.01, 4.61] */
#define BIN_W (5.0f / 4096.0f)
#define BPI 37                      /* chunks per image; 37*16 = 592 = 4*148 SMs */
#define THREADS 256

// ---------------- scratch (static device, zero-init is valid identity) ----------------
__device__ unsigned long long g_winner[B_ * G_];   // 0 == no candidate (-> anchor 0)
__device__ unsigned int       g_hist[B_ * NBINS];
__device__ int                g_np[B_];
__device__ float              g_pos[B_];
__device__ float              g_locs[B_];
__device__ unsigned int       g_done[B_];
__device__ float              g_tot_loc;
__device__ float              g_tot_conf;
__device__ int                g_tot_np;
__device__ unsigned int       g_ctr;

// ---------------- helpers ----------------
__device__ __forceinline__ float warpReduceSumF(float v) {
    #pragma unroll
    for (int o = 16; o; o >>= 1) v += __shfl_down_sync(0xFFFFFFFFu, v, o);
    return v;
}
__device__ __forceinline__ int warpReduceSumI(int v) {
    #pragma unroll
    for (int o = 16; o; o >>= 1) v += __shfl_down_sync(0xFFFFFFFFu, v, o);
    return v;
}
__device__ __forceinline__ float sl1(float d) {
    float a = fabsf(d);
    return (a < 1.f) ? 0.5f * a * a : a - 0.5f;
}
__device__ __forceinline__ float loc_of(const float4 bp, float gcx, float gcy,
                                        float gsx, float gsy) {
    float pcx = (bp.x + bp.z) * 0.5f, pcy = (bp.y + bp.w) * 0.5f;
    float psx = bp.z - bp.x,          psy = bp.w - bp.y;
    return sl1(pcx - gcx) + sl1(pcy - gcy) + sl1(psx - gsx) + sl1(psy - gsy);
}
// bin of a negative anchor's BCE. MUST be used identically in main + fixup.
__device__ __forceinline__ int neg_bin(float p) {
    float v = -__logf(1.0f - p);          // fast log; error << bin width
    int bin = (int)(v * BIN_SCALE);
    return min(max(bin, 0), NBINS - 1);
}

// ---------------- single fused kernel ----------------
__global__ void __launch_bounds__(THREADS, 4)
k_all(const float4* __restrict__ anchors, const float*  __restrict__ conf,
      const float4* __restrict__ bbox,    const float4* __restrict__ gtb,
      float* __restrict__ out) {
    __shared__ float4 sgt[G_];
    __shared__ float  sareaG[G_];
    __shared__ float  sfhalf[G_];          // conservative filter: <= 0.5 * column max iou
    __shared__ float2 sgc[G_], sgs[G_];
    __shared__ unsigned long long sw[G_];
    __shared__ unsigned int shist[NBINS];
    __shared__ unsigned int warpTot[8];
    __shared__ float redF[8];
    __shared__ int   s_flag, s_np, sh_t;
    __shared__ float s_pos, s_loc, s_negpart;

    const int b    = blockIdx.y;
    const int tid  = threadIdx.x;
    const int wid  = tid >> 5, lane = tid & 31;

    for (int i = tid; i < NBINS; i += THREADS) shist[i] = 0u;
    if (tid < G_) {
        float4 g = gtb[b * G_ + tid];
        sgt[tid]    = g;
        sareaG[tid] = (g.z - g.x) * (g.w - g.y);
        sgc[tid] = make_float2((g.x + g.z) * 0.5f, (g.y + g.w) * 0.5f);
        sgs[tid] = make_float2(g.z - g.x, g.w - g.y);
        sw[tid]  = 0ull;
        sfhalf[tid] = 0.f;
    }
    __syncthreads();

    // ================= main phase =================
    // uneven per-image chunks: [c*A/BPI, (c+1)*A/BPI) -- exact cover of A_
    const int astart = (int)(((long long)blockIdx.x * A_) / BPI);
    const int aend   = (int)(((long long)(blockIdx.x + 1) * A_) / BPI);
    const int NIT    = (aend - astart + THREADS - 1) / THREADS;   // uniform per block
    const int gbase  = b * A_;
    float accP = 0.f, accL = 0.f; int accN = 0;

    #pragma unroll 1
    for (int it = 0; it < NIT; it++) {
        const int a     = astart + it * THREADS + tid;
        const bool valid = (a < aend);
        const int a_c   = valid ? a : (aend - 1);      // clamp for safe loads
        const float4 ab = anchors[gbase + a_c];
        const float  p  = conf[gbase + a_c];
        const float  aA = (ab.z - ab.x) * (ab.w - ab.y);

        float bi = -1.f, Sb = 1.f; int bidx = 0;       // first g always wins

        #pragma unroll 8
        for (int g = 0; g < G_; g++) {
            const float4 gb = sgt[g];
            const float  aG = sareaG[g];
            float lx = fmaxf(ab.x, gb.x), ly = fmaxf(ab.y, gb.y);
            float rx = fminf(ab.z, gb.z), ry = fminf(ab.w, gb.w);
            float w  = fmaxf(rx - lx, 0.f), h = fmaxf(ry - ly, 0.f);
            float inter = w * h;
            float S     = aA + aG;                     // inter + union
            // argmax over g: iou_new > iou_best  <=>  inter*Sb > bi*S
            bool better = inter * Sb > bi * S;
            bi   = better ? inter : bi;
            Sb   = better ? S     : Sb;
            bidx = better ? g     : bidx;
            // conservative per-GT winner filter (uni >= S/2 -> sfhalf*S <= cur*uni)
            float fh = ((volatile float*)sfhalf)[g];
            bool pass1 = valid && (inter > fh * S);
            if (__any_sync(0xFFFFFFFFu, pass1)) {      // warp-collective rare path
                float curf = __uint_as_float(((volatile unsigned int*)sw)[2 * g + 1]);
                float uni  = S - inter;
                bool pass2 = pass1 && (inter > curf * uni);
                unsigned long long pk = 0ull;
                if (pass2) {
                    float iou = __fdiv_rn(inter, uni);
                    pk = ((unsigned long long)__float_as_uint(iou) << 32)
                       | (unsigned int)(0xFFFFFFFFu - (unsigned int)a);
                }
                #pragma unroll
                for (int o = 16; o; o >>= 1) {
                    unsigned long long other = __shfl_down_sync(0xFFFFFFFFu, pk, o);
                    pk = (other > pk) ? other : pk;
                }
                if (lane == 0 && pk != 0ull) {
                    atomicMax(&sw[g], pk);
                    float wiou = __uint_as_float((unsigned int)(pk >> 32));
                    float nh = 0.5f * wiou;
                    if (nh > sfhalf[g]) sfhalf[g] = nh;   // racy fmax, conservative
                }
            }
        }

        if (valid) {
            const bool pos = 3.f * bi > Sb;            // iou > 0.5
            if (pos) {
                accN += 1;
                accP += -__logf(p);
                float4 bp = bbox[gbase + a_c];
                float2 gc = sgc[bidx], gs = sgs[bidx];
                accL += loc_of(bp, gc.x, gc.y, gs.x, gs.y);
            } else {
                atomicAdd(&shist[neg_bin(p)], 1u);
            }
        }
    }

    // ================= block epilogue: merge to globals =================
    accP = warpReduceSumF(accP);
    accL = warpReduceSumF(accL);
    accN = warpReduceSumI(accN);
    if (lane == 0) {
        if (accN)        atomicAdd(&g_np[b], accN);
        if (accP != 0.f) atomicAdd(&g_pos[b], accP);
        if (accL != 0.f) atomicAdd(&g_locs[b], accL);
    }
    __syncthreads();
    if (tid < G_ && sw[tid] != 0ull)
        atomicMax(&g_winner[b * G_ + tid], sw[tid]);
    for (int i = tid; i < NBINS; i += THREADS)
        if (shist[i]) atomicAdd(&g_hist[b * NBINS + i], shist[i]);

    __threadfence();
    __syncthreads();
    if (tid == 0) {
        unsigned old = atomicAdd(&g_done[b], 1u);
        s_flag = (old == (unsigned)(BPI - 1)) ? 1 : 0;
    }
    __syncthreads();
    if (!s_flag) return;

    // ================= fin phase (last block of image b) =================
    __threadfence();
    for (int i = tid; i < NBINS; i += THREADS) {
        shist[i] = g_hist[b * NBINS + i];
        g_hist[b * NBINS + i] = 0u;          // self-clean for next replay
    }
    if (tid == 0) {
        s_np  = g_np[b];   g_np[b]   = 0;
        s_pos = g_pos[b];  g_pos[b]  = 0.f;
        s_loc = g_locs[b]; g_locs[b] = 0.f;
        g_done[b] = 0u;
        sh_t = 0x7FFFFFFF; s_negpart = 0.f;
    }
    __syncthreads();

    // ---- force-match fixup (warp 0, lane = gt index) ----
    if (tid < 32) {
        unsigned long long w = g_winner[b * G_ + lane];
        g_winner[b * G_ + lane] = 0ull;      // self-clean
        unsigned int a = (w == 0ull) ? 0u
                       : (0xFFFFFFFFu - (unsigned int)(w & 0xFFFFFFFFull));
        unsigned int grp = __match_any_sync(0xFFFFFFFFu, a);
        bool leader = ((grp & ((1u << lane) - 1u)) == 0u);
        if (leader) {
            const int idx = b * A_ + (int)a;
            const float4 ab = anchors[idx];
            const float aA = (ab.z - ab.x) * (ab.w - ab.y);
            float bi = -1.f, Sb = 1.f; int bidx = 0;
            #pragma unroll 8
            for (int g = 0; g < G_; g++) {
                const float4 gb = sgt[g];
                float lx = fmaxf(ab.x, gb.x), ly = fmaxf(ab.y, gb.y);
                float rx = fminf(ab.z, gb.z), ry = fminf(ab.w, gb.w);
                float ww = fmaxf(rx - lx, 0.f), hh = fmaxf(ry - ly, 0.f);
                float inter = ww * hh;
                float S     = aA + sareaG[g];
                bool better = inter * Sb > bi * S;
                bi = better ? inter : bi; Sb = better ? S : Sb; bidx = better ? g : bidx;
            }
            if (!(3.f * bi > Sb)) {
                // main phase counted this anchor as negative -> move to positives
                float p = conf[idx];
                atomicAdd(&s_np, 1);
                atomicAdd(&s_pos, -__logf(p));
                float4 bp = bbox[idx];
                float2 gc = sgc[bidx], gs = sgs[bidx];
                atomicAdd(&s_loc, loc_of(bp, gc.x, gc.y, gs.x, gs.y));
                atomicSub(&shist[neg_bin(p)], 1u);
            }
        }
    }
    __syncthreads();

    const int np = s_np;
    const int K  = min(3 * np, A_ - np);

    // ---- parallel suffix scan; each thread owns 16 bins ----
    unsigned c = 0u; float wsum = 0.f;
    #pragma unroll
    for (int k = 0; k < 16; k++) {
        int bin = tid * 16 + k;
        unsigned v = shist[bin];
        c += v;
        wsum += (float)v * ((bin + 0.5f) * BIN_W);
    }
    unsigned x = c;
    #pragma unroll
    for (int off = 1; off < 32; off <<= 1) {
        unsigned y = __shfl_down_sync(0xFFFFFFFFu, x, off);
        if (lane + off < 32) x += y;
    }
    if (lane == 0) warpTot[wid] = x;
    __syncthreads();
    unsigned wsuf = 0u;
    #pragma unroll
    for (int w = 0; w < 8; w++) if (w > wid) wsuf += warpTot[w];
    const unsigned S_incl = x + wsuf;
    const unsigned S_excl = S_incl - c;

    if (K > 0 && (int)S_excl < K && (int)S_incl >= K) {
        unsigned acc = S_excl;
        float part = 0.f;
        #pragma unroll 1
        for (int j = 15; j >= 0; j--) {
            int bin = tid * 16 + j;
            unsigned cnt = shist[bin];
            if ((int)(acc + cnt) >= K) {
                part += (float)(K - (int)acc) * ((bin + 0.5f) * BIN_W);
                break;
            }
            acc += cnt;
            part += (float)cnt * ((bin + 0.5f) * BIN_W);
        }
        s_negpart = part;
        sh_t = tid;
    }
    __syncthreads();

    float contrib = (tid > sh_t) ? wsum : 0.f;
    contrib = warpReduceSumF(contrib);
    if (lane == 0) redF[wid] = contrib;
    __syncthreads();

    if (tid == 0) {
        float neg = s_negpart;
        #pragma unroll
        for (int i = 0; i < 8; i++) neg += redF[i];
        float conf_b = s_pos / (float)max(np, 1) + neg / (float)max(K, 1);
        atomicAdd(&g_tot_conf, conf_b);
        atomicAdd(&g_tot_loc, s_loc);
        atomicAdd(&g_tot_np, np);
        __threadfence();
        unsigned done = atomicAdd(&g_ctr, 1u);
        if (done == (unsigned)(B_ - 1)) {
            __threadfence();
            float tl = *(volatile float*)&g_tot_loc;
            float tc = *(volatile float*)&g_tot_conf;
            int   tn = *(volatile int*)  &g_tot_np;
            out[0] = tl / (float)max(tn, 1) + tc / (float)B_;
            g_tot_loc = 0.f; g_tot_conf = 0.f; g_tot_np = 0; g_ctr = 0u;
        }
    }
}

// ---------------- launch ----------------
extern "C" void kernel_launch(void* const* d_in, const int* in_sizes, int n_in,
                              void* d_out, int out_size) {
    const float4* bbox    = (const float4*)d_in[0];   // [B,A,4]
    const float*  conf    = (const float*) d_in[1];   // [B,A]
    const float4* anchors = (const float4*)d_in[2];   // [B,A,4]
    const float4* gtb     = (const float4*)d_in[3];   // [B,G,4]
    (void)in_sizes; (void)n_in; (void)out_size;

    k_all<<<dim3(BPI, B_), THREADS>>>(anchors, conf, bbox, gtb, (float*)d_out);
}

// round 10
// speedup vs baseline: 1.0464x; 1.0464x over previous
#include <cuda_runtime.h>

// ---------------- problem constants ----------------
#define B_  16
#define A_  65536
#define G_  32
#define NBINS 4096
#define BIN_SCALE 819.2f            /* NBINS / 5.0 ; bce in [0.01, 4.61] */
#define BIN_W (5.0f / 4096.0f)
#define BPI 16                      /* blocks per image */
#define THREADS 512
#define PER (A_ / BPI)              /* 4096 anchors per block */
#define GROUPS (PER / (THREADS * 4))/* 2 groups of 4 anchors per thread */

// ---------------- scratch (static device, zero-init is valid identity) ----------------
__device__ unsigned long long g_winner[B_ * G_];   // 0 == no candidate (-> anchor 0)
__device__ unsigned int       g_hist[B_ * NBINS];
__device__ int                g_np[B_];
__device__ float              g_pos[B_];
__device__ float              g_locs[B_];
__device__ unsigned int       g_done[B_];
__device__ float              g_tot_loc;
__device__ float              g_tot_conf;
__device__ int                g_tot_np;
__device__ unsigned int       g_ctr;

// ---------------- helpers ----------------
__device__ __forceinline__ float warpReduceSumF(float v) {
    #pragma unroll
    for (int o = 16; o; o >>= 1) v += __shfl_down_sync(0xFFFFFFFFu, v, o);
    return v;
}
__device__ __forceinline__ int warpReduceSumI(int v) {
    #pragma unroll
    for (int o = 16; o; o >>= 1) v += __shfl_down_sync(0xFFFFFFFFu, v, o);
    return v;
}
__device__ __forceinline__ float sl1(float d) {
    float a = fabsf(d);
    return (a < 1.f) ? 0.5f * a * a : a - 0.5f;
}
__device__ __forceinline__ float loc_of(const float4 bp, float gcx, float gcy,
                                        float gsx, float gsy) {
    float pcx = (bp.x + bp.z) * 0.5f, pcy = (bp.y + bp.w) * 0.5f;
    float psx = bp.z - bp.x,          psy = bp.w - bp.y;
    return sl1(pcx - gcx) + sl1(pcy - gcy) + sl1(psx - gsx) + sl1(psy - gsy);
}
// bin of a negative anchor's BCE. MUST be used identically in main + fixup.
__device__ __forceinline__ int neg_bin(float p) {
    float v = -__logf(1.0f - p);          // fast log; error << bin width
    int bin = (int)(v * BIN_SCALE);
    return min(max(bin, 0), NBINS - 1);
}
// argmax of iou over all GTs via cross-multiply chain (first-max tiebreak).
// Used by BOTH the positive second pass and the fixup phase.
__device__ __forceinline__ int argmax_g(const float4 ab, float aA,
                                        const float4* sgt, const float* sareaG,
                                        float& bi_out, float& Sb_out) {
    float bi = -1.f, Sb = 1.f; int bidx = 0;
    #pragma unroll 8
    for (int g = 0; g < G_; g++) {
        const float4 gb = sgt[g];
        float lx = fmaxf(ab.x, gb.x), ly = fmaxf(ab.y, gb.y);
        float rx = fminf(ab.z, gb.z), ry = fminf(ab.w, gb.w);
        float w  = fmaxf(rx - lx, 0.f), h = fmaxf(ry - ly, 0.f);
        float inter = w * h;
        float S     = aA + sareaG[g];
        bool better = inter * Sb > bi * S;
        bi = better ? inter : bi; Sb = better ? S : Sb; bidx = better ? g : bidx;
    }
    bi_out = bi; Sb_out = Sb;
    return bidx;
}

// ---------------- single fused kernel ----------------
__global__ void __launch_bounds__(THREADS, 2)
k_all(const float4* __restrict__ anchors, const float*  __restrict__ conf,
      const float4* __restrict__ bbox,    const float4* __restrict__ gtb,
      float* __restrict__ out) {
    __shared__ float4 sgt[G_];
    __shared__ float  sareaG[G_];
    __shared__ float2 sgc[G_], sgs[G_];
    __shared__ unsigned long long sw[G_];
    __shared__ unsigned int shist[NBINS];
    __shared__ unsigned int warpTot[16];
    __shared__ float redF[16];
    __shared__ int   s_flag, s_np, sh_t;
    __shared__ float s_pos, s_loc, s_negpart;

    const int b    = blockIdx.y;
    const int tid  = threadIdx.x;
    const int wid  = tid >> 5, lane = tid & 31;

    for (int i = tid; i < NBINS; i += THREADS) shist[i] = 0u;
    if (tid < G_) {
        float4 g = gtb[b * G_ + tid];
        sgt[tid]    = g;
        sareaG[tid] = (g.z - g.x) * (g.w - g.y);
        sgc[tid] = make_float2((g.x + g.z) * 0.5f, (g.y + g.w) * 0.5f);
        sgs[tid] = make_float2(g.z - g.x, g.w - g.y);
        sw[tid]  = 0ull;
    }
    __syncthreads();

    // ================= main phase =================
    const int base  = blockIdx.x * PER;
    const int gbase = b * A_;
    float accP = 0.f, accL = 0.f; int accN = 0;

    #pragma unroll 1
    for (int grp = 0; grp < GROUPS; grp++) {
        const int a0 = base + grp * (THREADS * 4) + tid;
        float4 ab[4]; float aA[4]; bool pos[4];
        #pragma unroll
        for (int k = 0; k < 4; k++) {
            ab[k]  = anchors[gbase + a0 + k * THREADS];
            aA[k]  = (ab[k].z - ab[k].x) * (ab[k].w - ab[k].y);
            pos[k] = false;
        }

        #pragma unroll 4
        for (int g = 0; g < G_; g++) {
            const float4 gb = sgt[g];
            const float  aG = sareaG[g];
            const float  curf = __uint_as_float(((volatile unsigned int*)sw)[2 * g + 1]);
            #pragma unroll
            for (int k = 0; k < 4; k++) {
                float lx = fmaxf(ab[k].x, gb.x), ly = fmaxf(ab[k].y, gb.y);
                float rx = fminf(ab[k].z, gb.z), ry = fminf(ab[k].w, gb.w);
                float w  = fmaxf(rx - lx, 0.f),  h  = fmaxf(ry - ly, 0.f);
                float inter = w * h;
                float S     = aA[k] + aG;                  // inter + union
                pos[k] |= (3.f * inter > S);               // iou > 0.5 (FSETP.OR)
                float uni = S - inter;
                if (inter > curf * uni) {                  // rare
                    float iou = __fdiv_rn(inter, uni);
                    unsigned int a = (unsigned int)(a0 + k * THREADS);
                    unsigned long long pk =
                        ((unsigned long long)__float_as_uint(iou) << 32)
                        | (unsigned int)(0xFFFFFFFFu - a);
                    atomicMax(&sw[g], pk);
                }
            }
        }

        #pragma unroll
        for (int k = 0; k < 4; k++) {
            const int idx = gbase + a0 + k * THREADS;
            const float p = conf[idx];
            if (pos[k]) {
                // rare: recompute argmax to find the matched GT
                float bi, Sb;
                int bidx = argmax_g(ab[k], aA[k], sgt, sareaG, bi, Sb);
                accN += 1;
                accP += -__logf(p);
                float4 bp = bbox[idx];
                float2 gc = sgc[bidx], gs = sgs[bidx];
                accL += loc_of(bp, gc.x, gc.y, gs.x, gs.y);
            } else {
                atomicAdd(&shist[neg_bin(p)], 1u);
            }
        }
    }

    // ================= block epilogue: merge to globals =================
    accP = warpReduceSumF(accP);
    accL = warpReduceSumF(accL);
    accN = warpReduceSumI(accN);
    if (lane == 0) {
        if (accN)        atomicAdd(&g_np[b], accN);
        if (accP != 0.f) atomicAdd(&g_pos[b], accP);
        if (accL != 0.f) atomicAdd(&g_locs[b], accL);
    }
    __syncthreads();
    if (tid < G_ && sw[tid] != 0ull)
        atomicMax(&g_winner[b * G_ + tid], sw[tid]);
    for (int i = tid; i < NBINS; i += THREADS)
        if (shist[i]) atomicAdd(&g_hist[b * NBINS + i], shist[i]);

    __threadfence();
    __syncthreads();
    if (tid == 0) {
        unsigned old = atomicAdd(&g_done[b], 1u);
        s_flag = (old == (unsigned)(BPI - 1)) ? 1 : 0;
    }
    __syncthreads();
    if (!s_flag) return;

    // ================= fin phase (last block of image b) =================
    __threadfence();
    for (int i = tid; i < NBINS; i += THREADS) {
        shist[i] = g_hist[b * NBINS + i];
        g_hist[b * NBINS + i] = 0u;          // self-clean for next replay
    }
    if (tid == 0) {
        s_np  = g_np[b];   g_np[b]   = 0;
        s_pos = g_pos[b];  g_pos[b]  = 0.f;
        s_loc = g_locs[b]; g_locs[b] = 0.f;
        g_done[b] = 0u;
        sh_t = 0x7FFFFFFF; s_negpart = 0.f;
    }
    __syncthreads();

    // ---- force-match fixup (warp 0, lane = gt index) ----
    if (tid < 32) {
        unsigned long long w = g_winner[b * G_ + lane];
        g_winner[b * G_ + lane] = 0ull;      // self-clean
        unsigned int a = (w == 0ull) ? 0u
                       : (0xFFFFFFFFu - (unsigned int)(w & 0xFFFFFFFFull));
        unsigned int grp = __match_any_sync(0xFFFFFFFFu, a);
        bool leader = ((grp & ((1u << lane) - 1u)) == 0u);
        if (leader) {
            const int idx = b * A_ + (int)a;
            const float4 ab = anchors[idx];
            const float aA = (ab.z - ab.x) * (ab.w - ab.y);
            float bi, Sb;
            int bidx = argmax_g(ab, aA, sgt, sareaG, bi, Sb);
            if (!(3.f * bi > Sb)) {
                // main phase counted this anchor as negative -> move to positives
                float p = conf[idx];
                atomicAdd(&s_np, 1);
                atomicAdd(&s_pos, -__logf(p));
                float4 bp = bbox[idx];
                float2 gc = sgc[bidx], gs = sgs[bidx];
                atomicAdd(&s_loc, loc_of(bp, gc.x, gc.y, gs.x, gs.y));
                atomicSub(&shist[neg_bin(p)], 1u);
            }
        }
    }
    __syncthreads();

    const int np = s_np;
    const int K  = min(3 * np, A_ - np);

    // ---- parallel suffix scan; each thread owns 8 bins ----
    unsigned c = 0u; float wsum = 0.f;
    #pragma unroll
    for (int k = 0; k < 8; k++) {
        int bin = tid * 8 + k;
        unsigned v = shist[bin];
        c += v;
        wsum += (float)v * ((bin + 0.5f) * BIN_W);
    }
    unsigned x = c;
    #pragma unroll
    for (int off = 1; off < 32; off <<= 1) {
        unsigned y = __shfl_down_sync(0xFFFFFFFFu, x, off);
        if (lane + off < 32) x += y;
    }
    if (lane == 0) warpTot[wid] = x;
    __syncthreads();
    unsigned wsuf = 0u;
    #pragma unroll
    for (int w = 0; w < 16; w++) if (w > wid) wsuf += warpTot[w];
    const unsigned S_incl = x + wsuf;
    const unsigned S_excl = S_incl - c;

    if (K > 0 && (int)S_excl < K && (int)S_incl >= K) {
        unsigned acc = S_excl;
        float part = 0.f;
        #pragma unroll 1
        for (int j = 7; j >= 0; j--) {
            int bin = tid * 8 + j;
            unsigned cnt = shist[bin];
            if ((int)(acc + cnt) >= K) {
                part += (float)(K - (int)acc) * ((bin + 0.5f) * BIN_W);
                break;
            }
            acc += cnt;
            part += (float)cnt * ((bin + 0.5f) * BIN_W);
        }
        s_negpart = part;
        sh_t = tid;
    }
    __syncthreads();

    float contrib = (tid > sh_t) ? wsum : 0.f;
    contrib = warpReduceSumF(contrib);
    if (lane == 0) redF[wid] = contrib;
    __syncthreads();

    if (tid == 0) {
        float neg = s_negpart;
        #pragma unroll
        for (int i = 0; i < 16; i++) neg += redF[i];
        float conf_b = s_pos / (float)max(np, 1) + neg / (float)max(K, 1);
        atomicAdd(&g_tot_conf, conf_b);
        atomicAdd(&g_tot_loc, s_loc);
        atomicAdd(&g_tot_np, np);
        __threadfence();
        unsigned done = atomicAdd(&g_ctr, 1u);
        if (done == (unsigned)(B_ - 1)) {
            __threadfence();
            float tl = *(volatile float*)&g_tot_loc;
            float tc = *(volatile float*)&g_tot_conf;
            int   tn = *(volatile int*)  &g_tot_np;
            out[0] = tl / (float)max(tn, 1) + tc / (float)B_;
            g_tot_loc = 0.f; g_tot_conf = 0.f; g_tot_np = 0; g_ctr = 0u;
        }
    }
}

// ---------------- launch ----------------
extern "C" void kernel_launch(void* const* d_in, const int* in_sizes, int n_in,
                              void* d_out, int out_size) {
    const float4* bbox    = (const float4*)d_in[0];   // [B,A,4]
    const float*  conf    = (const float*) d_in[1];   // [B,A]
    const float4* anchors = (const float4*)d_in[2];   // [B,A,4]
    const float4* gtb     = (const float4*)d_in[3];   // [B,G,4]
    (void)in_sizes; (void)n_in; (void)out_size;

    k_all<<<dim3(BPI, B_), THREADS>>>(anchors, conf, bbox, gtb, (float*)d_out);
}

// round 11
// speedup vs baseline: 1.2526x; 1.1970x over previous
#include <cuda_runtime.h>

// ---------------- problem constants ----------------
#define B_  16
#define A_  65536
#define G_  32
#define NBINS 4096
#define BIN_SCALE 819.2f            /* NBINS / 5.0 ; bce in [0.01, 4.61] */
#define BIN_W (5.0f / 4096.0f)
#define BPI 16                      /* blocks per image */
#define THREADS 512
#define PER (A_ / BPI)              /* 4096 anchors per block */
#define GROUPS (PER / (THREADS * 4))/* 2 groups of 4 anchors per thread */
#define FULL 0xFFFFFFFFu

// ---------------- scratch (static device, zero-init is valid identity) ----------------
__device__ unsigned long long g_winner[B_ * G_];   // 0 == no candidate (-> anchor 0)
__device__ unsigned int       g_hist[B_ * NBINS];
__device__ int                g_np[B_];
__device__ float              g_pos[B_];
__device__ float              g_locs[B_];
__device__ unsigned int       g_done[B_];
__device__ float              g_tot_loc;
__device__ float              g_tot_conf;
__device__ int                g_tot_np;
__device__ unsigned int       g_ctr;

// ---------------- helpers ----------------
__device__ __forceinline__ float warpReduceSumF(float v) {
    #pragma unroll
    for (int o = 16; o; o >>= 1) v += __shfl_down_sync(FULL, v, o);
    return v;
}
__device__ __forceinline__ int warpReduceSumI(int v) {
    #pragma unroll
    for (int o = 16; o; o >>= 1) v += __shfl_down_sync(FULL, v, o);
    return v;
}
__device__ __forceinline__ float sl1(float d) {
    float a = fabsf(d);
    return (a < 1.f) ? 0.5f * a * a : a - 0.5f;
}
__device__ __forceinline__ float loc_of(const float4 bp, float gcx, float gcy,
                                        float gsx, float gsy) {
    float pcx = (bp.x + bp.z) * 0.5f, pcy = (bp.y + bp.w) * 0.5f;
    float psx = bp.z - bp.x,          psy = bp.w - bp.y;
    return sl1(pcx - gcx) + sl1(pcy - gcy) + sl1(psx - gsx) + sl1(psy - gsy);
}
// bin of a negative anchor's BCE. MUST be used identically in main + fixup.
__device__ __forceinline__ int neg_bin(float p) {
    float v = -__logf(1.0f - p);          // fast log; error << bin width
    int bin = (int)(v * BIN_SCALE);
    return min(max(bin, 0), NBINS - 1);
}

// ---------------- single fused kernel ----------------
__global__ void __launch_bounds__(THREADS, 2)
k_all(const float4* __restrict__ anchors, const float*  __restrict__ conf,
      const float4* __restrict__ bbox,    const float4* __restrict__ gtb,
      float* __restrict__ out) {
    __shared__ float4 sgt[G_];
    __shared__ float  sareaG[G_];
    __shared__ float2 sgc[G_], sgs[G_];
    __shared__ unsigned long long sw[G_];
    __shared__ unsigned int shist[NBINS];
    __shared__ unsigned int warpTot[16];
    __shared__ float redF[16];
    __shared__ int   s_flag, s_np, sh_t;
    __shared__ float s_pos, s_loc, s_negpart;

    const int b    = blockIdx.y;
    const int tid  = threadIdx.x;
    const int wid  = tid >> 5, lane = tid & 31;

    for (int i = tid; i < NBINS; i += THREADS) shist[i] = 0u;
    if (tid < G_) {
        float4 g = gtb[b * G_ + tid];
        sgt[tid]    = g;
        sareaG[tid] = (g.z - g.x) * (g.w - g.y);
        sgc[tid] = make_float2((g.x + g.z) * 0.5f, (g.y + g.w) * 0.5f);
        sgs[tid] = make_float2(g.z - g.x, g.w - g.y);
        sw[tid]  = 0ull;
    }
    __syncthreads();

    // ================= main phase =================
    const int base  = blockIdx.x * PER;
    const int gbase = b * A_;
    float accP = 0.f, accL = 0.f; int accN = 0;

    #pragma unroll 1
    for (int grp = 0; grp < GROUPS; grp++) {
        const int a0 = base + grp * (THREADS * 4) + tid;
        float4 ab[4]; float aA[4]; float posm[4];
        #pragma unroll
        for (int k = 0; k < 4; k++) {
            ab[k]   = anchors[gbase + a0 + k * THREADS];
            aA[k]   = (ab[k].z - ab[k].x) * (ab[k].w - ab[k].y);
            posm[k] = -1.f;
        }

        #pragma unroll 4
        for (int g = 0; g < G_; g++) {
            const float4 gb = sgt[g];
            const float  aG = sareaG[g];
            // halfcur = 0.5 * current winner iou for this gt (exact halving).
            // Filter inter > halfcur*S is a NECESSARY cond for inter > cur*uni
            // since uni >= S/2; superset passes are deduped by atomicMax.
            const float halfcur =
                0.5f * __uint_as_float(((volatile unsigned int*)sw)[2 * g + 1]);
            #pragma unroll
            for (int k = 0; k < 4; k++) {
                float lx = fmaxf(ab[k].x, gb.x), ly = fmaxf(ab[k].y, gb.y);
                float rx = fminf(ab[k].z, gb.z), ry = fminf(ab[k].w, gb.w);
                float w  = fmaxf(rx - lx, 0.f),  h  = fmaxf(ry - ly, 0.f);
                float inter = w * h;
                float S     = aA[k] + aG;                   // inter + union
                // sign-exact positivity: 3*inter - S > 0  <=>  iou > 0.5
                posm[k] = fmaxf(posm[k], fmaf(3.f, inter, -S));
                if (fmaf(-halfcur, S, inter) > 0.f) {       // rare
                    float uni   = S - inter;
                    float curf  = 2.f * halfcur;            // exact
                    if (inter > curf * uni) {
                        float iou = __fdiv_rn(inter, uni);
                        unsigned int a = (unsigned int)(a0 + k * THREADS);
                        unsigned long long pk =
                            ((unsigned long long)__float_as_uint(iou) << 32)
                            | (unsigned int)(FULL - a);
                        atomicMax(&sw[g], pk);
                    }
                }
            }
        }

        // ---- group epilogue: negatives -> histogram; positives -> warp-collective ----
        #pragma unroll
        for (int k = 0; k < 4; k++) {
            const bool ispos = posm[k] > 0.f;
            if (!ispos) {
                const float p = conf[gbase + a0 + k * THREADS];
                atomicAdd(&shist[neg_bin(p)], 1u);
            }
            unsigned m = __ballot_sync(FULL, ispos);
            while (m) {                           // expected ~0.6 total per warp/group
                int src = __ffs((int)m) - 1; m &= m - 1;
                float abx = __shfl_sync(FULL, ab[k].x, src);
                float aby = __shfl_sync(FULL, ab[k].y, src);
                float abz = __shfl_sync(FULL, ab[k].z, src);
                float abw = __shfl_sync(FULL, ab[k].w, src);
                float aAs = __shfl_sync(FULL, aA[k], src);
                // each lane evaluates gt g = lane
                const float4 gb = sgt[lane];
                float lx = fmaxf(abx, gb.x), ly = fmaxf(aby, gb.y);
                float rx = fminf(abz, gb.z), ry = fminf(abw, gb.w);
                float w  = fmaxf(rx - lx, 0.f), h = fmaxf(ry - ly, 0.f);
                float bi = w * h;
                float Sb = aAs + sareaG[lane];
                int   bg = lane;
                // cross-multiply argmax reduce; keep-current-on-tie => lowest g
                #pragma unroll
                for (int off = 16; off; off >>= 1) {
                    float oi = __shfl_down_sync(FULL, bi, off);
                    float oS = __shfl_down_sync(FULL, Sb, off);
                    int   og = __shfl_down_sync(FULL, bg, off);
                    bool bet = oi * Sb > bi * oS;
                    bi = bet ? oi : bi; Sb = bet ? oS : Sb; bg = bet ? og : bg;
                }
                if (lane == 0) {
                    int sa   = (a0 - tid) + (wid * 32 + src) + k * THREADS;
                    int sidx = gbase + sa;
                    float p  = conf[sidx];
                    accN += 1;
                    accP += -__logf(p);
                    float4 bp = bbox[sidx];
                    float2 gc = sgc[bg], gs = sgs[bg];
                    accL += loc_of(bp, gc.x, gc.y, gs.x, gs.y);
                }
            }
        }
    }

    // ================= block epilogue: merge to globals =================
    accP = warpReduceSumF(accP);
    accL = warpReduceSumF(accL);
    accN = warpReduceSumI(accN);
    if (lane == 0) {
        if (accN)        atomicAdd(&g_np[b], accN);
        if (accP != 0.f) atomicAdd(&g_pos[b], accP);
        if (accL != 0.f) atomicAdd(&g_locs[b], accL);
    }
    __syncthreads();
    if (tid < G_ && sw[tid] != 0ull)
        atomicMax(&g_winner[b * G_ + tid], sw[tid]);
    for (int i = tid; i < NBINS; i += THREADS)
        if (shist[i]) atomicAdd(&g_hist[b * NBINS + i], shist[i]);

    __threadfence();
    __syncthreads();
    if (tid == 0) {
        unsigned old = atomicAdd(&g_done[b], 1u);
        s_flag = (old == (unsigned)(BPI - 1)) ? 1 : 0;
    }
    __syncthreads();
    if (!s_flag) return;

    // ================= fin phase (last block of image b) =================
    __threadfence();
    for (int i = tid; i < NBINS; i += THREADS) {
        shist[i] = g_hist[b * NBINS + i];
        g_hist[b * NBINS + i] = 0u;          // self-clean for next replay
    }
    if (tid == 0) {
        s_np  = g_np[b];   g_np[b]   = 0;
        s_pos = g_pos[b];  g_pos[b]  = 0.f;
        s_loc = g_locs[b]; g_locs[b] = 0.f;
        g_done[b] = 0u;
        sh_t = 0x7FFFFFFF; s_negpart = 0.f;
    }
    __syncthreads();

    // ---- force-match fixup (warp 0, lane = gt index) ----
    if (tid < 32) {
        unsigned long long w = g_winner[b * G_ + lane];
        g_winner[b * G_ + lane] = 0ull;      // self-clean
        unsigned int a = (w == 0ull) ? 0u
                       : (FULL - (unsigned int)(w & 0xFFFFFFFFull));
        unsigned int grp = __match_any_sync(FULL, a);
        bool leader = ((grp & ((1u << lane) - 1u)) == 0u);
        if (leader) {
            const int idx = b * A_ + (int)a;
            const float4 ab = anchors[idx];
            const float aA = (ab.z - ab.x) * (ab.w - ab.y);
            float bi = -1.f, Sb = 1.f; int bidx = 0; float posm = -1.f;
            #pragma unroll 8
            for (int g = 0; g < G_; g++) {
                const float4 gb = sgt[g];
                float lx = fmaxf(ab.x, gb.x), ly = fmaxf(ab.y, gb.y);
                float rx = fminf(ab.z, gb.z), ry = fminf(ab.w, gb.w);
                float ww = fmaxf(rx - lx, 0.f), hh = fmaxf(ry - ly, 0.f);
                float inter = ww * hh;
                float S     = aA + sareaG[g];
                posm = fmaxf(posm, fmaf(3.f, inter, -S));   // same as main phase
                bool better = inter * Sb > bi * S;
                bi = better ? inter : bi; Sb = better ? S : Sb; bidx = better ? g : bidx;
            }
            if (!(posm > 0.f)) {
                // main phase counted this anchor as negative -> move to positives
                float p = conf[idx];
                atomicAdd(&s_np, 1);
                atomicAdd(&s_pos, -__logf(p));
                float4 bp = bbox[idx];
                float2 gc = sgc[bidx], gs = sgs[bidx];
                atomicAdd(&s_loc, loc_of(bp, gc.x, gc.y, gs.x, gs.y));
                atomicSub(&shist[neg_bin(p)], 1u);
            }
        }
    }
    __syncthreads();

    const int np = s_np;
    const int K  = min(3 * np, A_ - np);

    // ---- parallel suffix scan; each thread owns 8 bins ----
    unsigned c = 0u; float wsum = 0.f;
    #pragma unroll
    for (int k = 0; k < 8; k++) {
        int bin = tid * 8 + k;
        unsigned v = shist[bin];
        c += v;
        wsum += (float)v * ((bin + 0.5f) * BIN_W);
    }
    unsigned x = c;
    #pragma unroll
    for (int off = 1; off < 32; off <<= 1) {
        unsigned y = __shfl_down_sync(FULL, x, off);
        if (lane + off < 32) x += y;
    }
    if (lane == 0) warpTot[wid] = x;
    __syncthreads();
    unsigned wsuf = 0u;
    #pragma unroll
    for (int w = 0; w < 16; w++) if (w > wid) wsuf += warpTot[w];
    const unsigned S_incl = x + wsuf;
    const unsigned S_excl = S_incl - c;

    if (K > 0 && (int)S_excl < K && (int)S_incl >= K) {
        unsigned acc = S_excl;
        float part = 0.f;
        #pragma unroll 1
        for (int j = 7; j >= 0; j--) {
            int bin = tid * 8 + j;
            unsigned cnt = shist[bin];
            if ((int)(acc + cnt) >= K) {
                part += (float)(K - (int)acc) * ((bin + 0.5f) * BIN_W);
                break;
            }
            acc += cnt;
            part += (float)cnt * ((bin + 0.5f) * BIN_W);
        }
        s_negpart = part;
        sh_t = tid;
    }
    __syncthreads();

    float contrib = (tid > sh_t) ? wsum : 0.f;
    contrib = warpReduceSumF(contrib);
    if (lane == 0) redF[wid] = contrib;
    __syncthreads();

    if (tid == 0) {
        float neg = s_negpart;
        #pragma unroll
        for (int i = 0; i < 16; i++) neg += redF[i];
        float conf_b = s_pos / (float)max(np, 1) + neg / (float)max(K, 1);
        atomicAdd(&g_tot_conf, conf_b);
        atomicAdd(&g_tot_loc, s_loc);
        atomicAdd(&g_tot_np, np);
        __threadfence();
        unsigned done = atomicAdd(&g_ctr, 1u);
        if (done == (unsigned)(B_ - 1)) {
            __threadfence();
            float tl = *(volatile float*)&g_tot_loc;
            float tc = *(volatile float*)&g_tot_conf;
            int   tn = *(volatile int*)  &g_tot_np;
            out[0] = tl / (float)max(tn, 1) + tc / (float)B_;
            g_tot_loc = 0.f; g_tot_conf = 0.f; g_tot_np = 0; g_ctr = 0u;
        }
    }
}

// ---------------- launch ----------------
extern "C" void kernel_launch(void* const* d_in, const int* in_sizes, int n_in,
                              void* d_out, int out_size) {
    const float4* bbox    = (const float4*)d_in[0];   // [B,A,4]
    const float*  conf    = (const float*) d_in[1];   // [B,A]
    const float4* anchors = (const float4*)d_in[2];   // [B,A,4]
    const float4* gtb     = (const float4*)d_in[3];   // [B,G,4]
    (void)in_sizes; (void)n_in; (void)out_size;

    k_all<<<dim3(BPI, B_), THREADS>>>(anchors, conf, bbox, gtb, (float*)d_out);
}

// round 12
// speedup vs baseline: 1.2663x; 1.0109x over previous
#include <cuda_runtime.h>

// ---------------- problem constants ----------------
#define B_  16
#define A_  65536
#define G_  32
#define NBINS 4096
#define BIN_SCALE 819.2f            /* NBINS / 5.0 ; bce in [0.01, 4.61] */
#define BIN_W (5.0f / 4096.0f)
#define BPI 16                      /* blocks per image */
#define THREADS 512
#define PER (A_ / BPI)              /* 4096 anchors per block */
#define GROUPS (PER / (THREADS * 4))/* 2 groups of 4 anchors per thread */
#define FULL 0xFFFFFFFFu

// ---------------- scratch (static device, zero-init is valid identity) ----------------
__device__ unsigned long long g_winner[B_ * G_];   // 0 == no candidate (-> anchor 0)
__device__ unsigned int       g_hist[B_ * NBINS];
__device__ int                g_np[B_];
__device__ float              g_pos[B_];
__device__ float              g_locs[B_];
__device__ unsigned int       g_done[B_];
__device__ float              g_tot_loc;
__device__ float              g_tot_conf;
__device__ int                g_tot_np;
__device__ unsigned int       g_ctr;

// ---------------- helpers ----------------
__device__ __forceinline__ float warpReduceSumF(float v) {
    #pragma unroll
    for (int o = 16; o; o >>= 1) v += __shfl_down_sync(FULL, v, o);
    return v;
}
__device__ __forceinline__ int warpReduceSumI(int v) {
    #pragma unroll
    for (int o = 16; o; o >>= 1) v += __shfl_down_sync(FULL, v, o);
    return v;
}
__device__ __forceinline__ float sl1(float d) {
    float a = fabsf(d);
    return (a < 1.f) ? 0.5f * a * a : a - 0.5f;
}
__device__ __forceinline__ float loc_of(const float4 bp, float gcx, float gcy,
                                        float gsx, float gsy) {
    float pcx = (bp.x + bp.z) * 0.5f, pcy = (bp.y + bp.w) * 0.5f;
    float psx = bp.z - bp.x,          psy = bp.w - bp.y;
    return sl1(pcx - gcx) + sl1(pcy - gcy) + sl1(psx - gsx) + sl1(psy - gsy);
}
// bin of a negative anchor's BCE. MUST be used identically in main + fixup.
__device__ __forceinline__ int neg_bin(float p) {
    float v = -__logf(1.0f - p);          // fast log; error << bin width
    int bin = (int)(v * BIN_SCALE);
    return min(max(bin, 0), NBINS - 1);
}

// ---------------- single fused kernel ----------------
__global__ void __launch_bounds__(THREADS, 2)
k_all(const float4* __restrict__ anchors, const float*  __restrict__ conf,
      const float4* __restrict__ bbox,    const float4* __restrict__ gtb,
      float* __restrict__ out) {
    __shared__ float4 sgt[G_];
    __shared__ float  sareaG[G_];
    __shared__ float  st[G_];              // filter threshold: <= curf/(1+curf)
    __shared__ float2 sgc[G_], sgs[G_];
    __shared__ unsigned long long sw[G_];
    __shared__ unsigned int shist[NBINS];
    __shared__ unsigned int warpTot[16];
    __shared__ float redF[16];
    __shared__ int   s_flag, s_np, sh_t;
    __shared__ float s_pos, s_loc, s_negpart;

    const int b    = blockIdx.y;
    const int tid  = threadIdx.x;
    const int wid  = tid >> 5, lane = tid & 31;

    for (int i = tid; i < NBINS; i += THREADS) shist[i] = 0u;
    if (tid < G_) {
        float4 g = gtb[b * G_ + tid];
        sgt[tid]    = g;
        sareaG[tid] = (g.z - g.x) * (g.w - g.y);
        sgc[tid] = make_float2((g.x + g.z) * 0.5f, (g.y + g.w) * 0.5f);
        sgs[tid] = make_float2(g.z - g.x, g.w - g.y);
        sw[tid]  = 0ull;
        st[tid]  = 0.f;
    }
    __syncthreads();

    // ================= main phase =================
    const int base  = blockIdx.x * PER;
    const int gbase = b * A_;
    float accP = 0.f, accL = 0.f; int accN = 0;

    #pragma unroll 1
    for (int grp = 0; grp < GROUPS; grp++) {
        const int a0 = base + grp * (THREADS * 4) + tid;
        float4 ab[4]; float aA[4]; float posm[4]; float pc[4];
        #pragma unroll
        for (int k = 0; k < 4; k++) {
            ab[k]   = anchors[gbase + a0 + k * THREADS];
            pc[k]   = conf[gbase + a0 + k * THREADS];   // prefetch, hidden by g-loop
            aA[k]   = (ab[k].z - ab[k].x) * (ab[k].w - ab[k].y);
            posm[k] = -1.f;
        }

        #pragma unroll 4
        for (int g = 0; g < G_; g++) {
            const float4 gb = sgt[g];
            const float  aG = sareaG[g];
            // t <= curf/(1+curf): exact-strength filter, division-free in hot loop.
            // inter > curf*uni  <=>  inter > S*curf/(1+curf)  >=  S*t.
            const float t = ((volatile float*)st)[g];
            #pragma unroll
            for (int k = 0; k < 4; k++) {
                float lx = fmaxf(ab[k].x, gb.x), ly = fmaxf(ab[k].y, gb.y);
                float rx = fminf(ab[k].z, gb.z), ry = fminf(ab[k].w, gb.w);
                float w  = fmaxf(rx - lx, 0.f),  h  = fmaxf(ry - ly, 0.f);
                float inter = w * h;
                float S     = aA[k] + aG;                   // inter + union
                // sign-exact positivity: 3*inter - S > 0  <=>  iou > 0.5
                posm[k] = fmaxf(posm[k], fmaf(3.f, inter, -S));
                if (fmaf(-t, S, inter) > 0.f) {             // rare (exact-strength)
                    float curf = __uint_as_float(
                        ((volatile unsigned int*)sw)[2 * g + 1]);
                    float uni  = S - inter;
                    if (inter > curf * uni) {               // exact winner check
                        float iou = __fdiv_rn(inter, uni);
                        unsigned int a = (unsigned int)(a0 + k * THREADS);
                        unsigned long long pk =
                            ((unsigned long long)__float_as_uint(iou) << 32)
                            | (unsigned int)(FULL - a);
                        atomicMax(&sw[g], pk);
                        // racy monotone threshold update (conservative: any
                        // stale/lost write only lowers the filter threshold)
                        float tn = __fdividef(iou, 1.0f + iou) * 0.9999999f;
                        if (tn > st[g]) st[g] = tn;
                    }
                }
            }
        }

        // ---- group epilogue: negatives -> histogram; positives -> warp-collective ----
        #pragma unroll
        for (int k = 0; k < 4; k++) {
            const bool ispos = posm[k] > 0.f;
            if (!ispos) {
                atomicAdd(&shist[neg_bin(pc[k])], 1u);
            }
            unsigned m = __ballot_sync(FULL, ispos);
            while (m) {                           // expected ~0.6 total per warp/group
                int src = __ffs((int)m) - 1; m &= m - 1;
                float abx = __shfl_sync(FULL, ab[k].x, src);
                float aby = __shfl_sync(FULL, ab[k].y, src);
                float abz = __shfl_sync(FULL, ab[k].z, src);
                float abw = __shfl_sync(FULL, ab[k].w, src);
                float aAs = __shfl_sync(FULL, aA[k], src);
                float ps  = __shfl_sync(FULL, pc[k], src);
                // each lane evaluates gt g = lane
                const float4 gb = sgt[lane];
                float lx = fmaxf(abx, gb.x), ly = fmaxf(aby, gb.y);
                float rx = fminf(abz, gb.z), ry = fminf(abw, gb.w);
                float w  = fmaxf(rx - lx, 0.f), h = fmaxf(ry - ly, 0.f);
                float bi = w * h;
                float Sb = aAs + sareaG[lane];
                int   bg = lane;
                // cross-multiply argmax reduce; keep-current-on-tie => lowest g
                #pragma unroll
                for (int off = 16; off; off >>= 1) {
                    float oi = __shfl_down_sync(FULL, bi, off);
                    float oS = __shfl_down_sync(FULL, Sb, off);
                    int   og = __shfl_down_sync(FULL, bg, off);
                    bool bet = oi * Sb > bi * oS;
                    bi = bet ? oi : bi; Sb = bet ? oS : Sb; bg = bet ? og : bg;
                }
                if (lane == 0) {
                    int sa   = (a0 - tid) + (wid * 32 + src) + k * THREADS;
                    int sidx = gbase + sa;
                    accN += 1;
                    accP += -__logf(ps);
                    float4 bp = bbox[sidx];
                    float2 gc = sgc[bg], gs = sgs[bg];
                    accL += loc_of(bp, gc.x, gc.y, gs.x, gs.y);
                }
            }
        }
    }

    // ================= block epilogue: merge to globals =================
    accP = warpReduceSumF(accP);
    accL = warpReduceSumF(accL);
    accN = warpReduceSumI(accN);
    if (lane == 0) {
        if (accN)        atomicAdd(&g_np[b], accN);
        if (accP != 0.f) atomicAdd(&g_pos[b], accP);
        if (accL != 0.f) atomicAdd(&g_locs[b], accL);
    }
    __syncthreads();
    if (tid < G_ && sw[tid] != 0ull)
        atomicMax(&g_winner[b * G_ + tid], sw[tid]);
    for (int i = tid; i < NBINS; i += THREADS)
        if (shist[i]) atomicAdd(&g_hist[b * NBINS + i], shist[i]);

    __threadfence();
    __syncthreads();
    if (tid == 0) {
        unsigned old = atomicAdd(&g_done[b], 1u);
        s_flag = (old == (unsigned)(BPI - 1)) ? 1 : 0;
    }
    __syncthreads();
    if (!s_flag) return;

    // ================= fin phase (last block of image b) =================
    __threadfence();
    for (int i = tid; i < NBINS; i += THREADS) {
        shist[i] = g_hist[b * NBINS + i];
        g_hist[b * NBINS + i] = 0u;          // self-clean for next replay
    }
    if (tid == 0) {
        s_np  = g_np[b];   g_np[b]   = 0;
        s_pos = g_pos[b];  g_pos[b]  = 0.f;
        s_loc = g_locs[b]; g_locs[b] = 0.f;
        g_done[b] = 0u;
        sh_t = 0x7FFFFFFF; s_negpart = 0.f;
    }
    __syncthreads();

    // ---- force-match fixup (warp 0, lane = gt index) ----
    if (tid < 32) {
        unsigned long long w = g_winner[b * G_ + lane];
        g_winner[b * G_ + lane] = 0ull;      // self-clean
        unsigned int a = (w == 0ull) ? 0u
                       : (FULL - (unsigned int)(w & 0xFFFFFFFFull));
        unsigned int grp = __match_any_sync(FULL, a);
        bool leader = ((grp & ((1u << lane) - 1u)) == 0u);
        if (leader) {
            const int idx = b * A_ + (int)a;
            const float4 ab = anchors[idx];
            const float aA = (ab.z - ab.x) * (ab.w - ab.y);
            float bi = -1.f, Sb = 1.f; int bidx = 0; float posm = -1.f;
            #pragma unroll 8
            for (int g = 0; g < G_; g++) {
                const float4 gb = sgt[g];
                float lx = fmaxf(ab.x, gb.x), ly = fmaxf(ab.y, gb.y);
                float rx = fminf(ab.z, gb.z), ry = fminf(ab.w, gb.w);
                float ww = fmaxf(rx - lx, 0.f), hh = fmaxf(ry - ly, 0.f);
                float inter = ww * hh;
                float S     = aA + sareaG[g];
                posm = fmaxf(posm, fmaf(3.f, inter, -S));   // same as main phase
                bool better = inter * Sb > bi * S;
                bi = better ? inter : bi; Sb = better ? S : Sb; bidx = better ? g : bidx;
            }
            if (!(posm > 0.f)) {
                // main phase counted this anchor as negative -> move to positives
                float p = conf[idx];
                atomicAdd(&s_np, 1);
                atomicAdd(&s_pos, -__logf(p));
                float4 bp = bbox[idx];
                float2 gc = sgc[bidx], gs = sgs[bidx];
                atomicAdd(&s_loc, loc_of(bp, gc.x, gc.y, gs.x, gs.y));
                atomicSub(&shist[neg_bin(p)], 1u);
            }
        }
    }
    __syncthreads();

    const int np = s_np;
    const int K  = min(3 * np, A_ - np);

    // ---- parallel suffix scan; each thread owns 8 bins ----
    unsigned c = 0u; float wsum = 0.f;
    #pragma unroll
    for (int k = 0; k < 8; k++) {
        int bin = tid * 8 + k;
        unsigned v = shist[bin];
        c += v;
        wsum += (float)v * ((bin + 0.5f) * BIN_W);
    }
    unsigned x = c;
    #pragma unroll
    for (int off = 1; off < 32; off <<= 1) {
        unsigned y = __shfl_down_sync(FULL, x, off);
        if (lane + off < 32) x += y;
    }
    if (lane == 0) warpTot[wid] = x;
    __syncthreads();
    unsigned wsuf = 0u;
    #pragma unroll
    for (int w = 0; w < 16; w++) if (w > wid) wsuf += warpTot[w];
    const unsigned S_incl = x + wsuf;
    const unsigned S_excl = S_incl - c;

    if (K > 0 && (int)S_excl < K && (int)S_incl >= K) {
        unsigned acc = S_excl;
        float part = 0.f;
        #pragma unroll 1
        for (int j = 7; j >= 0; j--) {
            int bin = tid * 8 + j;
            unsigned cnt = shist[bin];
            if ((int)(acc + cnt) >= K) {
                part += (float)(K - (int)acc) * ((bin + 0.5f) * BIN_W);
                break;
            }
            acc += cnt;
            part += (float)cnt * ((bin + 0.5f) * BIN_W);
        }
        s_negpart = part;
        sh_t = tid;
    }
    __syncthreads();

    float contrib = (tid > sh_t) ? wsum : 0.f;
    contrib = warpReduceSumF(contrib);
    if (lane == 0) redF[wid] = contrib;
    __syncthreads();

    if (tid == 0) {
        float neg = s_negpart;
        #pragma unroll
        for (int i = 0; i < 16; i++) neg += redF[i];
        float conf_b = s_pos / (float)max(np, 1) + neg / (float)max(K, 1);
        atomicAdd(&g_tot_conf, conf_b);
        atomicAdd(&g_tot_loc, s_loc);
        atomicAdd(&g_tot_np, np);
        __threadfence();
        unsigned done = atomicAdd(&g_ctr, 1u);
        if (done == (unsigned)(B_ - 1)) {
            __threadfence();
            float tl = *(volatile float*)&g_tot_loc;
            float tc = *(volatile float*)&g_tot_conf;
            int   tn = *(volatile int*)  &g_tot_np;
            out[0] = tl / (float)max(tn, 1) + tc / (float)B_;
            g_tot_loc = 0.f; g_tot_conf = 0.f; g_tot_np = 0; g_ctr = 0u;
        }
    }
}

// ---------------- launch ----------------
extern "C" void kernel_launch(void* const* d_in, const int* in_sizes, int n_in,
                              void* d_out, int out_size) {
    const float4* bbox    = (const float4*)d_in[0];   // [B,A,4]
    const float*  conf    = (const float*) d_in[1];   // [B,A]
    const float4* anchors = (const float4*)d_in[2];   // [B,A,4]
    const float4* gtb     = (const float4*)d_in[3];   // [B,G,4]
    (void)in_sizes; (void)n_in; (void)out_size;

    k_all<<<dim3(BPI, B_), THREADS>>>(anchors, conf, bbox, gtb, (float*)d_out);
}

// round 13
// speedup vs baseline: 1.3970x; 1.1033x over previous
#include <cuda_runtime.h>

// ---------------- problem constants ----------------
#define B_  16
#define A_  65536
#define G_  32
#define NBINS 4096
#define BIN_SCALE 819.2f            /* NBINS / 5.0 ; bce in [0.01, 4.61] */
#define BIN_W (5.0f / 4096.0f)
#define BPI 16                      /* blocks per image */
#define THREADS 512                 /* 16 warps */
#define NW (THREADS / 32)
#define PER (A_ / BPI)              /* 4096 anchors per block */
#define PERW (PER / NW)             /* 256 anchors per warp */
#define CHUNKS (PERW / 32)          /* 8 chunks of 32 */
#define FULL 0xFFFFFFFFu

// ---------------- scratch (static device, zero-init is valid identity) ----------------
__device__ unsigned long long g_winner[B_ * G_];   // 0 == no candidate (-> anchor 0)
__device__ unsigned int       g_hist[B_ * NBINS];
__device__ int                g_np[B_];
__device__ float              g_pos[B_];
__device__ float              g_locs[B_];
__device__ unsigned int       g_done[B_];
__device__ float              g_tot_loc;
__device__ float              g_tot_conf;
__device__ int                g_tot_np;
__device__ unsigned int       g_ctr;

// ---------------- helpers ----------------
__device__ __forceinline__ float warpReduceSumF(float v) {
    #pragma unroll
    for (int o = 16; o; o >>= 1) v += __shfl_down_sync(FULL, v, o);
    return v;
}
__device__ __forceinline__ int warpReduceSumI(int v) {
    #pragma unroll
    for (int o = 16; o; o >>= 1) v += __shfl_down_sync(FULL, v, o);
    return v;
}
__device__ __forceinline__ float sl1(float d) {
    float a = fabsf(d);
    return (a < 1.f) ? 0.5f * a * a : a - 0.5f;
}
__device__ __forceinline__ float loc_of(const float4 bp, float gcx, float gcy,
                                        float gsx, float gsy) {
    float pcx = (bp.x + bp.z) * 0.5f, pcy = (bp.y + bp.w) * 0.5f;
    float psx = bp.z - bp.x,          psy = bp.w - bp.y;
    return sl1(pcx - gcx) + sl1(pcy - gcy) + sl1(psx - gsx) + sl1(psy - gsy);
}
// bin of a negative anchor's BCE. MUST be used identically in main + fixup.
__device__ __forceinline__ int neg_bin(float p) {
    float v = -__logf(1.0f - p);          // fast log; error << bin width
    int bin = (int)(v * BIN_SCALE);
    return min(max(bin, 0), NBINS - 1);
}

// ---------------- single fused kernel ----------------
__global__ void __launch_bounds__(THREADS, 2)
k_all(const float4* __restrict__ anchors, const float*  __restrict__ conf,
      const float4* __restrict__ bbox,    const float4* __restrict__ gtb,
      float* __restrict__ out) {
    __shared__ float4 sgt[G_];
    __shared__ float  sareaG[G_];
    __shared__ float2 sgc[G_], sgs[G_];
    __shared__ unsigned long long sw[G_];
    __shared__ unsigned int shist[NBINS];
    __shared__ float4 sAnch[NW][32];       // per-warp anchor staging
    __shared__ float  sAa[NW][32];         // per-warp anchor areas
    __shared__ unsigned int warpTot[NW];
    __shared__ float redF[NW];
    __shared__ int   s_flag, s_np, sh_t;
    __shared__ float s_pos, s_loc, s_negpart;

    const int b    = blockIdx.y;
    const int tid  = threadIdx.x;
    const int wid  = tid >> 5, lane = tid & 31;

    for (int i = tid; i < NBINS; i += THREADS) shist[i] = 0u;
    if (tid < G_) {
        float4 g = gtb[b * G_ + tid];
        sgt[tid]    = g;
        sareaG[tid] = (g.z - g.x) * (g.w - g.y);
        sgc[tid] = make_float2((g.x + g.z) * 0.5f, (g.y + g.w) * 0.5f);
        sgs[tid] = make_float2(g.z - g.x, g.w - g.y);
        sw[tid]  = 0ull;
    }
    __syncthreads();

    // ================= main phase: GT-per-lane transposed loop =================
    const int gbase = b * A_;
    const int wbase = blockIdx.x * PER + wid * PERW;   // within-image anchor base
    const float4 GL = sgt[lane];                       // my gt box (registers)
    const float  GA = sareaG[lane];
    float tb = 0.f;                                    // filter thr <= curf/(1+curf)
    unsigned long long wk = 0ull;                      // my gt best packed (iou, ~a)
    float accP = 0.f, accL = 0.f; int accN = 0;

    #pragma unroll 1
    for (int chunk = 0; chunk < CHUNKS; ++chunk) {
        const int abase = wbase + chunk * 32;
        const float4 myA = anchors[gbase + abase + lane];
        const float  myp = conf[gbase + abase + lane];
        __syncwarp();                                  // protect prior-chunk readers
        sAnch[wid][lane] = myA;
        sAa[wid][lane]   = (myA.z - myA.x) * (myA.w - myA.y);
        __syncwarp();

        unsigned pm = 0u, fm = 0u;
        #pragma unroll
        for (int r = 0; r < 32; ++r) {
            const float4 a  = sAnch[wid][r];           // LDS broadcast (N=1)
            const float  aA = sAa[wid][r];
            float lx = fmaxf(a.x, GL.x), ly = fmaxf(a.y, GL.y);
            float rx = fminf(a.z, GL.z), ry = fminf(a.w, GL.w);
            float w  = fmaxf(rx - lx, 0.f), h = fmaxf(ry - ly, 0.f);
            float inter = w * h;
            float S     = aA + GA;                     // inter + union
            if (fmaf(3.f, inter, -S) > 0.f) pm |= (1u << r);   // iou > 0.5
            if (fmaf(-tb, S, inter) > 0.f)  fm |= (1u << r);   // winner candidate
        }

        // ---- deferred rare path: winner candidates for my gt ----
        while (fm) {
            int r = __ffs((int)fm) - 1; fm &= fm - 1;
            const float4 a  = sAnch[wid][r];
            const float  aA = sAa[wid][r];
            float lx = fmaxf(a.x, GL.x), ly = fmaxf(a.y, GL.y);
            float rx = fminf(a.z, GL.z), ry = fminf(a.w, GL.w);
            float w  = fmaxf(rx - lx, 0.f), h = fmaxf(ry - ly, 0.f);
            float inter = w * h;
            float S     = aA + GA;
            float uni   = S - inter;
            float curw  = __uint_as_float((unsigned)(wk >> 32));
            if (inter > curw * uni) {                  // exact winner check
                float iou = __fdiv_rn(inter, uni);
                unsigned long long pk =
                    ((unsigned long long)__float_as_uint(iou) << 32)
                    | (unsigned)(FULL - (unsigned)(abase + r));
                if (pk > wk) wk = pk;
            }
        }
        // merge my winner + refresh filter from block-global best
        if (wk) atomicMax(&sw[lane], wk);
        {
            unsigned long long swv = *((volatile unsigned long long*)&sw[lane]);
            if (swv > wk) wk = swv;                    // aligned 8B read, no tearing
            float curM = __uint_as_float((unsigned)(wk >> 32));
            tb = __fdividef(curM, 1.f + curM) * 0.9999999f;  // strictly conservative
        }

        // ---- positivity epilogue ----
        unsigned posOR = __reduce_or_sync(FULL, pm);   // anchor r positive iff bit r
        bool mypos = (posOR >> lane) & 1u;
        if (!mypos) atomicAdd(&shist[neg_bin(myp)], 1u);

        unsigned m = posOR;
        while (m) {                                    // rare positives, collective
            int src = __ffs((int)m) - 1; m &= m - 1;
            const float4 a  = sAnch[wid][src];
            const float  aAs = sAa[wid][src];
            float ps = __shfl_sync(FULL, myp, src);
            // lane evaluates gt = lane
            float lx = fmaxf(a.x, GL.x), ly = fmaxf(a.y, GL.y);
            float rx = fminf(a.z, GL.z), ry = fminf(a.w, GL.w);
            float w  = fmaxf(rx - lx, 0.f), h = fmaxf(ry - ly, 0.f);
            float bi = w * h;
            float Sb = aAs + GA;
            int   bg = lane;
            // cross-multiply argmax reduce; keep-current-on-tie => lowest g
            #pragma unroll
            for (int off = 16; off; off >>= 1) {
                float oi = __shfl_down_sync(FULL, bi, off);
                float oS = __shfl_down_sync(FULL, Sb, off);
                int   og = __shfl_down_sync(FULL, bg, off);
                bool bet = oi * Sb > bi * oS;
                bi = bet ? oi : bi; Sb = bet ? oS : Sb; bg = bet ? og : bg;
            }
            if (lane == 0) {
                int sidx = gbase + abase + src;
                accN += 1;
                accP += -__logf(ps);
                float4 bp = bbox[sidx];
                float2 gc = sgc[bg], gs = sgs[bg];
                accL += loc_of(bp, gc.x, gc.y, gs.x, gs.y);
            }
        }
    }

    // ================= block epilogue: merge to globals =================
    accP = warpReduceSumF(accP);
    accL = warpReduceSumF(accL);
    accN = warpReduceSumI(accN);
    if (lane == 0) {
        if (accN)        atomicAdd(&g_np[b], accN);
        if (accP != 0.f) atomicAdd(&g_pos[b], accP);
        if (accL != 0.f) atomicAdd(&g_locs[b], accL);
    }
    __syncthreads();
    if (tid < G_ && sw[tid] != 0ull)
        atomicMax(&g_winner[b * G_ + tid], sw[tid]);
    for (int i = tid; i < NBINS; i += THREADS)
        if (shist[i]) atomicAdd(&g_hist[b * NBINS + i], shist[i]);

    __threadfence();
    __syncthreads();
    if (tid == 0) {
        unsigned old = atomicAdd(&g_done[b], 1u);
        s_flag = (old == (unsigned)(BPI - 1)) ? 1 : 0;
    }
    __syncthreads();
    if (!s_flag) return;

    // ================= fin phase (last block of image b) =================
    __threadfence();
    for (int i = tid; i < NBINS; i += THREADS) {
        shist[i] = g_hist[b * NBINS + i];
        g_hist[b * NBINS + i] = 0u;          // self-clean for next replay
    }
    if (tid == 0) {
        s_np  = g_np[b];   g_np[b]   = 0;
        s_pos = g_pos[b];  g_pos[b]  = 0.f;
        s_loc = g_locs[b]; g_locs[b] = 0.f;
        g_done[b] = 0u;
        sh_t = 0x7FFFFFFF; s_negpart = 0.f;
    }
    __syncthreads();

    // ---- force-match fixup (warp 0, lane = gt index) ----
    if (tid < 32) {
        unsigned long long w = g_winner[b * G_ + lane];
        g_winner[b * G_ + lane] = 0ull;      // self-clean
        unsigned int a = (w == 0ull) ? 0u
                       : (FULL - (unsigned int)(w & 0xFFFFFFFFull));
        unsigned int grp = __match_any_sync(FULL, a);
        bool leader = ((grp & ((1u << lane) - 1u)) == 0u);
        if (leader) {
            const int idx = b * A_ + (int)a;
            const float4 ab = anchors[idx];
            const float aA = (ab.z - ab.x) * (ab.w - ab.y);
            float bi = -1.f, Sb = 1.f; int bidx = 0; float posm = -1.f;
            #pragma unroll 8
            for (int g = 0; g < G_; g++) {
                const float4 gb = sgt[g];
                float lx = fmaxf(ab.x, gb.x), ly = fmaxf(ab.y, gb.y);
                float rx = fminf(ab.z, gb.z), ry = fminf(ab.w, gb.w);
                float ww = fmaxf(rx - lx, 0.f), hh = fmaxf(ry - ly, 0.f);
                float inter = ww * hh;
                float S     = aA + sareaG[g];
                posm = fmaxf(posm, fmaf(3.f, inter, -S));   // same as main phase
                bool better = inter * Sb > bi * S;
                bi = better ? inter : bi; Sb = better ? S : Sb; bidx = better ? g : bidx;
            }
            if (!(posm > 0.f)) {
                // main phase counted this anchor as negative -> move to positives
                float p = conf[idx];
                atomicAdd(&s_np, 1);
                atomicAdd(&s_pos, -__logf(p));
                float4 bp = bbox[idx];
                float2 gc = sgc[bidx], gs = sgs[bidx];
                atomicAdd(&s_loc, loc_of(bp, gc.x, gc.y, gs.x, gs.y));
                atomicSub(&shist[neg_bin(p)], 1u);
            }
        }
    }
    __syncthreads();

    const int np = s_np;
    const int K  = min(3 * np, A_ - np);

    // ---- parallel suffix scan; each thread owns 8 bins ----
    unsigned c = 0u; float wsum = 0.f;
    #pragma unroll
    for (int k = 0; k < 8; k++) {
        int bin = tid * 8 + k;
        unsigned v = shist[bin];
        c += v;
        wsum += (float)v * ((bin + 0.5f) * BIN_W);
    }
    unsigned x = c;
    #pragma unroll
    for (int off = 1; off < 32; off <<= 1) {
        unsigned y = __shfl_down_sync(FULL, x, off);
        if (lane + off < 32) x += y;
    }
    if (lane == 0) warpTot[wid] = x;
    __syncthreads();
    unsigned wsuf = 0u;
    #pragma unroll
    for (int w = 0; w < NW; w++) if (w > wid) wsuf += warpTot[w];
    const unsigned S_incl = x + wsuf;
    const unsigned S_excl = S_incl - c;

    if (K > 0 && (int)S_excl < K && (int)S_incl >= K) {
        unsigned acc = S_excl;
        float part = 0.f;
        #pragma unroll 1
        for (int j = 7; j >= 0; j--) {
            int bin = tid * 8 + j;
            unsigned cnt = shist[bin];
            if ((int)(acc + cnt) >= K) {
                part += (float)(K - (int)acc) * ((bin + 0.5f) * BIN_W);
                break;
            }
            acc += cnt;
            part += (float)cnt * ((bin + 0.5f) * BIN_W);
        }
        s_negpart = part;
        sh_t = tid;
    }
    __syncthreads();

    float contrib = (tid > sh_t) ? wsum : 0.f;
    contrib = warpReduceSumF(contrib);
    if (lane == 0) redF[wid] = contrib;
    __syncthreads();

    if (tid == 0) {
        float neg = s_negpart;
        #pragma unroll
        for (int i = 0; i < NW; i++) neg += redF[i];
        float conf_b = s_pos / (float)max(np, 1) + neg / (float)max(K, 1);
        atomicAdd(&g_tot_conf, conf_b);
        atomicAdd(&g_tot_loc, s_loc);
        atomicAdd(&g_tot_np, np);
        __threadfence();
        unsigned done = atomicAdd(&g_ctr, 1u);
        if (done == (unsigned)(B_ - 1)) {
            __threadfence();
            float tl = *(volatile float*)&g_tot_loc;
            float tc = *(volatile float*)&g_tot_conf;
            int   tn = *(volatile int*)  &g_tot_np;
            out[0] = tl / (float)max(tn, 1) + tc / (float)B_;
            g_tot_loc = 0.f; g_tot_conf = 0.f; g_tot_np = 0; g_ctr = 0u;
        }
    }
}

// ---------------- launch ----------------
extern "C" void kernel_launch(void* const* d_in, const int* in_sizes, int n_in,
                              void* d_out, int out_size) {
    const float4* bbox    = (const float4*)d_in[0];   // [B,A,4]
    const float*  conf    = (const float*) d_in[1];   // [B,A]
    const float4* anchors = (const float4*)d_in[2];   // [B,A,4]
    const float4* gtb     = (const float4*)d_in[3];   // [B,G,4]
    (void)in_sizes; (void)n_in; (void)out_size;

    k_all<<<dim3(BPI, B_), THREADS>>>(anchors, conf, bbox, gtb, (float*)d_out);
}

// round 14
// speedup vs baseline: 1.5003x; 1.0739x over previous
#include <cuda_runtime.h>

// ---------------- problem constants ----------------
#define B_  16
#define A_  65536
#define G_  32
#define NBINS 4096
#define BIN_SCALE 819.2f            /* NBINS / 5.0 ; bce in [0.01, 4.61] */
#define BIN_W (5.0f / 4096.0f)
#define BPI 16                      /* blocks per image */
#define THREADS 512                 /* 16 warps */
#define NW (THREADS / 32)
#define PER (A_ / BPI)              /* 4096 anchors per block */
#define PERW (PER / NW)             /* 256 anchors per warp */
#define CHUNKS (PERW / 32)          /* 8 chunks of 32 */
#define FULL 0xFFFFFFFFu

// ---------------- scratch (static device, zero-init is valid identity) ----------------
__device__ unsigned long long g_winner[B_ * G_];   // 0 == no candidate (-> anchor 0)
__device__ unsigned int       g_hist[B_ * NBINS];
__device__ int                g_np[B_];
__device__ float              g_pos[B_];
__device__ float              g_locs[B_];
__device__ unsigned int       g_done[B_];
__device__ float              g_tot_loc;
__device__ float              g_tot_conf;
__device__ int                g_tot_np;
__device__ unsigned int       g_ctr;

// ---------------- helpers ----------------
__device__ __forceinline__ float warpReduceSumF(float v) {
    #pragma unroll
    for (int o = 16; o; o >>= 1) v += __shfl_down_sync(FULL, v, o);
    return v;
}
__device__ __forceinline__ int warpReduceSumI(int v) {
    #pragma unroll
    for (int o = 16; o; o >>= 1) v += __shfl_down_sync(FULL, v, o);
    return v;
}
__device__ __forceinline__ float sl1(float d) {
    float a = fabsf(d);
    return (a < 1.f) ? 0.5f * a * a : a - 0.5f;
}
__device__ __forceinline__ float loc_of(const float4 bp, float gcx, float gcy,
                                        float gsx, float gsy) {
    float pcx = (bp.x + bp.z) * 0.5f, pcy = (bp.y + bp.w) * 0.5f;
    float psx = bp.z - bp.x,          psy = bp.w - bp.y;
    return sl1(pcx - gcx) + sl1(pcy - gcy) + sl1(psx - gsx) + sl1(psy - gsy);
}
// bin of a negative anchor's BCE. MUST be used identically in main + fixup.
__device__ __forceinline__ int neg_bin(float p) {
    float v = -__logf(1.0f - p);          // fast log; error << bin width
    int bin = (int)(v * BIN_SCALE);
    return min(max(bin, 0), NBINS - 1);
}

// ---------------- single fused kernel ----------------
__global__ void __launch_bounds__(THREADS, 2)
k_all(const float4* __restrict__ anchors, const float*  __restrict__ conf,
      const float4* __restrict__ bbox,    const float4* __restrict__ gtb,
      float* __restrict__ out) {
    __shared__ float4 sgt[G_];
    __shared__ float  sareaG[G_];
    __shared__ float2 sgc[G_], sgs[G_];
    __shared__ unsigned long long sw[G_];
    __shared__ unsigned int shist[NBINS];
    __shared__ float4 sAnch[NW][32];       // per-warp anchor staging
    __shared__ float  sAa[NW][32];         // per-warp anchor areas
    __shared__ unsigned int warpTot[NW];
    __shared__ float redF[NW];
    __shared__ int   s_flag, s_np, sh_t;
    __shared__ float s_pos, s_loc, s_negpart;

    const int b    = blockIdx.y;
    const int tid  = threadIdx.x;
    const int wid  = tid >> 5, lane = tid & 31;

    for (int i = tid; i < NBINS; i += THREADS) shist[i] = 0u;
    if (tid < G_) {
        float4 g = gtb[b * G_ + tid];
        sgt[tid]    = g;
        sareaG[tid] = (g.z - g.x) * (g.w - g.y);
        sgc[tid] = make_float2((g.x + g.z) * 0.5f, (g.y + g.w) * 0.5f);
        sgs[tid] = make_float2(g.z - g.x, g.w - g.y);
        sw[tid]  = 0ull;
    }
    __syncthreads();

    // ================= main phase: GT-per-lane transposed loop =================
    const int gbase = b * A_;
    const int wbase = blockIdx.x * PER + wid * PERW;   // within-image anchor base
    const float4 GL = sgt[lane];                       // my gt box (registers)
    const float  GA = sareaG[lane];
    float tb = 0.f;                                    // winner thr <= curf/(1+curf)
    float prevM = -1.f;                                // last seen winner iou
    unsigned long long wk = 0ull;                      // my gt best packed (iou, ~a)
    float accP = 0.f, accL = 0.f; int accN = 0;

    #pragma unroll 1
    for (int chunk = 0; chunk < CHUNKS; ++chunk) {
        const int abase = wbase + chunk * 32;
        const float4 myA = anchors[gbase + abase + lane];
        const float  myp = conf[gbase + abase + lane];
        __syncwarp();                                  // protect prior-chunk readers
        sAnch[wid][lane] = myA;
        sAa[wid][lane]   = (myA.z - myA.x) * (myA.w - myA.y);
        __syncwarp();

        // single combined flag: covers BOTH positives (inter > S/3) and
        // winner candidates (inter > tb*S), since tp <= min(tb, 1/3).
        const float tp = fminf(tb, 0.33333f);
        unsigned fm = 0u;
        #pragma unroll
        for (int r = 0; r < 32; ++r) {
            const float4 a  = sAnch[wid][r];           // LDS broadcast (N=1)
            const float  aA = sAa[wid][r];
            float lx = fmaxf(a.x, GL.x), ly = fmaxf(a.y, GL.y);
            float rx = fminf(a.z, GL.z), ry = fminf(a.w, GL.w);
            float w  = fmaxf(rx - lx, 0.f), h = fmaxf(ry - ly, 0.f);
            float inter = w * h;
            float S     = aA + GA;                     // inter + union
            if (fmaf(-tp, S, inter) > 0.f) fm |= (1u << r);
        }

        // ---- deferred rare path: classify flagged pairs exactly ----
        unsigned pm = 0u;
        const unsigned long long wk0 = wk;
        while (fm) {
            int r = __ffs((int)fm) - 1; fm &= fm - 1;
            const float4 a  = sAnch[wid][r];
            const float  aA = sAa[wid][r];
            float lx = fmaxf(a.x, GL.x), ly = fmaxf(a.y, GL.y);
            float rx = fminf(a.z, GL.z), ry = fminf(a.w, GL.w);
            float w  = fmaxf(rx - lx, 0.f), h = fmaxf(ry - ly, 0.f);
            float inter = w * h;
            float S     = aA + GA;
            if (fmaf(3.f, inter, -S) > 0.f) pm |= (1u << r);   // iou > 0.5 exact
            float uni  = S - inter;
            float curw = __uint_as_float((unsigned)(wk >> 32));
            if (inter > curw * uni) {                  // exact winner check
                float iou = __fdiv_rn(inter, uni);
                unsigned long long pk =
                    ((unsigned long long)__float_as_uint(iou) << 32)
                    | (unsigned)(FULL - (unsigned)(abase + r));
                if (pk > wk) wk = pk;
            }
        }
        // merge my winner (only if changed) + refresh filter threshold
        if (wk != wk0) atomicMax(&sw[lane], wk);
        {
            unsigned long long swv = *((volatile unsigned long long*)&sw[lane]);
            if (swv > wk) wk = swv;                    // aligned 8B read, no tearing
            float curM = __uint_as_float((unsigned)(wk >> 32));
            if (curM != prevM) {                       // rare after warm-up
                tb = __fdividef(curM, 1.f + curM) * 0.9999999f; // conservative
                prevM = curM;
            }
        }

        // ---- positivity epilogue ----
        unsigned posOR = __reduce_or_sync(FULL, pm);   // anchor r positive iff bit r
        bool mypos = (posOR >> lane) & 1u;
        if (!mypos) atomicAdd(&shist[neg_bin(myp)], 1u);

        unsigned m = posOR;
        while (m) {                                    // rare positives, collective
            int src = __ffs((int)m) - 1; m &= m - 1;
            const float4 a  = sAnch[wid][src];
            const float  aAs = sAa[wid][src];
            float ps = __shfl_sync(FULL, myp, src);
            // lane evaluates gt = lane
            float lx = fmaxf(a.x, GL.x), ly = fmaxf(a.y, GL.y);
            float rx = fminf(a.z, GL.z), ry = fminf(a.w, GL.w);
            float w  = fmaxf(rx - lx, 0.f), h = fmaxf(ry - ly, 0.f);
            float bi = w * h;
            float Sb = aAs + GA;
            int   bg = lane;
            // cross-multiply argmax reduce; keep-current-on-tie => lowest g
            #pragma unroll
            for (int off = 16; off; off >>= 1) {
                float oi = __shfl_down_sync(FULL, bi, off);
                float oS = __shfl_down_sync(FULL, Sb, off);
                int   og = __shfl_down_sync(FULL, bg, off);
                bool bet = oi * Sb > bi * oS;
                bi = bet ? oi : bi; Sb = bet ? oS : Sb; bg = bet ? og : bg;
            }
            if (lane == 0) {
                int sidx = gbase + abase + src;
                accN += 1;
                accP += -__logf(ps);
                float4 bp = bbox[sidx];
                float2 gc = sgc[bg], gs = sgs[bg];
                accL += loc_of(bp, gc.x, gc.y, gs.x, gs.y);
            }
        }
    }

    // ================= block epilogue: merge to globals =================
    accP = warpReduceSumF(accP);
    accL = warpReduceSumF(accL);
    accN = warpReduceSumI(accN);
    if (lane == 0) {
        if (accN)        atomicAdd(&g_np[b], accN);
        if (accP != 0.f) atomicAdd(&g_pos[b], accP);
        if (accL != 0.f) atomicAdd(&g_locs[b], accL);
    }
    __syncthreads();
    if (tid < G_ && sw[tid] != 0ull)
        atomicMax(&g_winner[b * G_ + tid], sw[tid]);
    for (int i = tid; i < NBINS; i += THREADS)
        if (shist[i]) atomicAdd(&g_hist[b * NBINS + i], shist[i]);

    __threadfence();
    __syncthreads();
    if (tid == 0) {
        unsigned old = atomicAdd(&g_done[b], 1u);
        s_flag = (old == (unsigned)(BPI - 1)) ? 1 : 0;
    }
    __syncthreads();
    if (!s_flag) return;

    // ================= fin phase (last block of image b) =================
    __threadfence();
    for (int i = tid; i < NBINS; i += THREADS) {
        shist[i] = g_hist[b * NBINS + i];
        g_hist[b * NBINS + i] = 0u;          // self-clean for next replay
    }
    if (tid == 0) {
        s_np  = g_np[b];   g_np[b]   = 0;
        s_pos = g_pos[b];  g_pos[b]  = 0.f;
        s_loc = g_locs[b]; g_locs[b] = 0.f;
        g_done[b] = 0u;
        sh_t = 0x7FFFFFFF; s_negpart = 0.f;
    }
    __syncthreads();

    // ---- force-match fixup (warp 0, lane = gt index) ----
    if (tid < 32) {
        unsigned long long w = g_winner[b * G_ + lane];
        g_winner[b * G_ + lane] = 0ull;      // self-clean
        unsigned int a = (w == 0ull) ? 0u
                       : (FULL - (unsigned int)(w & 0xFFFFFFFFull));
        unsigned int grp = __match_any_sync(FULL, a);
        bool leader = ((grp & ((1u << lane) - 1u)) == 0u);
        if (leader) {
            const int idx = b * A_ + (int)a;
            const float4 ab = anchors[idx];
            const float aA = (ab.z - ab.x) * (ab.w - ab.y);
            float bi = -1.f, Sb = 1.f; int bidx = 0; float posm = -1.f;
            #pragma unroll 8
            for (int g = 0; g < G_; g++) {
                const float4 gb = sgt[g];
                float lx = fmaxf(ab.x, gb.x), ly = fmaxf(ab.y, gb.y);
                float rx = fminf(ab.z, gb.z), ry = fminf(ab.w, gb.w);
                float ww = fmaxf(rx - lx, 0.f), hh = fmaxf(ry - ly, 0.f);
                float inter = ww * hh;
                float S     = aA + sareaG[g];
                posm = fmaxf(posm, fmaf(3.f, inter, -S));   // same as main phase
                bool better = inter * Sb > bi * S;
                bi = better ? inter : bi; Sb = better ? S : Sb; bidx = better ? g : bidx;
            }
            if (!(posm > 0.f)) {
                // main phase counted this anchor as negative -> move to positives
                float p = conf[idx];
                atomicAdd(&s_np, 1);
                atomicAdd(&s_pos, -__logf(p));
                float4 bp = bbox[idx];
                float2 gc = sgc[bidx], gs = sgs[bidx];
                atomicAdd(&s_loc, loc_of(bp, gc.x, gc.y, gs.x, gs.y));
                atomicSub(&shist[neg_bin(p)], 1u);
            }
        }
    }
    __syncthreads();

    const int np = s_np;
    const int K  = min(3 * np, A_ - np);

    // ---- parallel suffix scan; each thread owns 8 bins ----
    unsigned c = 0u; float wsum = 0.f;
    #pragma unroll
    for (int k = 0; k < 8; k++) {
        int bin = tid * 8 + k;
        unsigned v = shist[bin];
        c += v;
        wsum += (float)v * ((bin + 0.5f) * BIN_W);
    }
    unsigned x = c;
    #pragma unroll
    for (int off = 1; off < 32; off <<= 1) {
        unsigned y = __shfl_down_sync(FULL, x, off);
        if (lane + off < 32) x += y;
    }
    if (lane == 0) warpTot[wid] = x;
    __syncthreads();
    unsigned wsuf = 0u;
    #pragma unroll
    for (int w = 0; w < NW; w++) if (w > wid) wsuf += warpTot[w];
    const unsigned S_incl = x + wsuf;
    const unsigned S_excl = S_incl - c;

    if (K > 0 && (int)S_excl < K && (int)S_incl >= K) {
        unsigned acc = S_excl;
        float part = 0.f;
        #pragma unroll 1
        for (int j = 7; j >= 0; j--) {
            int bin = tid * 8 + j;
            unsigned cnt = shist[bin];
            if ((int)(acc + cnt) >= K) {
                part += (float)(K - (int)acc) * ((bin + 0.5f) * BIN_W);
                break;
            }
            acc += cnt;
            part += (float)cnt * ((bin + 0.5f) * BIN_W);
        }
        s_negpart = part;
        sh_t = tid;
    }
    __syncthreads();

    float contrib = (tid > sh_t) ? wsum : 0.f;
    contrib = warpReduceSumF(contrib);
    if (lane == 0) redF[wid] = contrib;
    __syncthreads();

    if (tid == 0) {
        float neg = s_negpart;
        #pragma unroll
        for (int i = 0; i < NW; i++) neg += redF[i];
        float conf_b = s_pos / (float)max(np, 1) + neg / (float)max(K, 1);
        atomicAdd(&g_tot_conf, conf_b);
        atomicAdd(&g_tot_loc, s_loc);
        atomicAdd(&g_tot_np, np);
        __threadfence();
        unsigned done = atomicAdd(&g_ctr, 1u);
        if (done == (unsigned)(B_ - 1)) {
            __threadfence();
            float tl = *(volatile float*)&g_tot_loc;
            float tc = *(volatile float*)&g_tot_conf;
            int   tn = *(volatile int*)  &g_tot_np;
            out[0] = tl / (float)max(tn, 1) + tc / (float)B_;
            g_tot_loc = 0.f; g_tot_conf = 0.f; g_tot_np = 0; g_ctr = 0u;
        }
    }
}

// ---------------- launch ----------------
extern "C" void kernel_launch(void* const* d_in, const int* in_sizes, int n_in,
                              void* d_out, int out_size) {
    const float4* bbox    = (const float4*)d_in[0];   // [B,A,4]
    const float*  conf    = (const float*) d_in[1];   // [B,A]
    const float4* anchors = (const float4*)d_in[2];   // [B,A,4]
    const float4* gtb     = (const float4*)d_in[3];   // [B,G,4]
    (void)in_sizes; (void)n_in; (void)out_size;

    k_all<<<dim3(BPI, B_), THREADS>>>(anchors, conf, bbox, gtb, (float*)d_out);
}